// round 5
// baseline (speedup 1.0000x reference)
#include <cuda_runtime.h>

#define BLOCK 256
#define NCTAS 888               // 148 SMs * 6 resident CTAs
#define LOG_CLAMP (-100.0f)
#define HDELTA 0.04f
#define FXSCALE 16777216.0      // 2^24 fixed-point scale
#define FULL 0xffffffffu

// Deterministic cross-CTA accumulation (integer adds are associative).
__device__ unsigned long long g_ce_acc = 0ULL;
__device__ unsigned long long g_hu_acc = 0ULL;
__device__ unsigned int       g_done   = 0u;

// log1p(-p) for small p via 5-term series (|err| < p^6/6).
__device__ __forceinline__ float log1mp_series(float p) {
    return -p * (1.0f + p * (0.5f + p * (0.33333333f + p * (0.25f + p * 0.2f))));
}

__device__ __forceinline__ float huber1(float x) {
    float ax = fabsf(x);
    float quad = 0.5f * x * x;
    float lin  = HDELTA * (ax - 0.5f * HDELTA);
    return (ax <= HDELTA) ? quad : lin;
}

__global__ void __launch_bounds__(BLOCK, 6)
loss_kernel(const float* __restrict__ anchors,
            const float* __restrict__ offsets,
            const float* __restrict__ conf,
            const float* __restrict__ gt,
            int N, int B,
            float* __restrict__ out)
{
    const int t    = threadIdx.x;
    const int lane = t & 31;
    const int warp = t >> 5;

    // Double-buffered per-warp partials: one barrier per row, and the
    // serial thread-0 fixup of row i overlaps warps 1..7 loading row i+1.
    __shared__ float swv[2][8];
    __shared__ int   swi[2][8];
    __shared__ float sp1[2][8], sp2[2][8], sp3[2][8];

    long long ce_fx = 0, hu_fx = 0;   // thread-0 local fixed-point accumulators
    int buf = 0;

    for (int b = blockIdx.x; b < B; b += gridDim.x, buf ^= 1) {
        const float2 g = ((const float2*)gt)[b];
        const float* __restrict__ arow = anchors + (size_t)b * (size_t)N * 2u;
        const float* __restrict__ crow = conf    + (size_t)b * (size_t)N;

        float best = 3.4e38f;
        int   bidx = 0;
        float p1 = 0.f, p2 = 0.f, p3 = 0.f;

        if (N == 2048) {
            // Front-batch all 6 wide loads (2x conf float4, 4x anchor float4).
            const float4* c4 = (const float4*)crow;
            const float4* a4 = (const float4*)arow;
            float4 cv0 = c4[t];
            float4 cv1 = c4[t + 256];

            #pragma unroll
            for (int j = 0; j < 4; j++) {
                int i4 = t + j * 256;            // float4 = anchors (2*i4, 2*i4+1)
                float4 a = a4[i4];
                float dx0 = a.x - g.x, dy0 = a.y - g.y;
                float dx1 = a.z - g.x, dy1 = a.w - g.y;
                float d0 = fmaf(dx0, dx0, dy0 * dy0);
                float d1 = fmaf(dx1, dx1, dy1 * dy1);
                // ascending per-thread indices: strict '<' keeps first occurrence
                if (d0 < best) { best = d0; bidx = 2 * i4; }
                if (d1 < best) { best = d1; bidx = 2 * i4 + 1; }
            }

            float c[8];
            c[0]=cv0.x; c[1]=cv0.y; c[2]=cv0.z; c[3]=cv0.w;
            c[4]=cv1.x; c[5]=cv1.y; c[6]=cv1.z; c[7]=cv1.w;
            #pragma unroll
            for (int i = 0; i < 8; i++) {
                float e  = __expf(c[i]);
                float e2 = e * e;
                p1 += e;
                p2 += e2;
                p3 += e2 * e;
            }
        } else {
            const float2* a2 = (const float2*)arow;
            for (int i = t; i < N; i += BLOCK) {
                float2 a = a2[i];
                float dx = a.x - g.x, dy = a.y - g.y;
                float d  = fmaf(dx, dx, dy * dy);
                if (d < best || (d == best && i < bidx)) { best = d; bidx = i; }
            }
            for (int i = t; i < N; i += BLOCK) {
                float e  = __expf(__ldg(crow + i));
                float e2 = e * e;
                p1 += e; p2 += e2; p3 += e2 * e;
            }
        }

        // Fused warp reduction (argmin pair + three sums).
        #pragma unroll
        for (int o = 16; o; o >>= 1) {
            float ov = __shfl_down_sync(FULL, best, o);
            int   oi = __shfl_down_sync(FULL, bidx, o);
            if (ov < best || (ov == best && oi < bidx)) { best = ov; bidx = oi; }
            p1 += __shfl_down_sync(FULL, p1, o);
            p2 += __shfl_down_sync(FULL, p2, o);
            p3 += __shfl_down_sync(FULL, p3, o);
        }
        if (lane == 0) {
            swv[buf][warp] = best; swi[buf][warp] = bidx;
            sp1[buf][warp] = p1;   sp2[buf][warp] = p2;   sp3[buf][warp] = p3;
        }
        __syncthreads();

        // Thread 0: combine, CE/Huber fixup, local fixed-point accumulate.
        // Warps 1..7 run ahead to the next row's loads immediately.
        if (t == 0) {
            float bb = swv[buf][0]; int bi = swi[buf][0];
            float P1 = sp1[buf][0], P2 = sp2[buf][0], P3 = sp3[buf][0];
            #pragma unroll
            for (int w = 1; w < 8; w++) {
                if (swv[buf][w] < bb || (swv[buf][w] == bb && swi[buf][w] < bi)) {
                    bb = swv[buf][w]; bi = swi[buf][w];
                }
                P1 += sp1[buf][w]; P2 += sp2[buf][w]; P3 += sp3[buf][w];
            }
            const int k = bi;

            float S = P1;
            float invS = __frcp_rn(S);
            float pmax_ub = __fsqrt_rn(P2) * invS;    // upper bound on max p_i
            float T, mm = 0.0f;
            if (isfinite(P3) && S > 0.0f && pmax_ub <= 0.03f) {
                // Normal path: T from power sums (P1/S == 1 exactly).
                float q2 = invS * invS;
                T = -(1.0f + 0.5f * P2 * q2 + 0.33333333f * P3 * q2 * invS);
            } else {
                // Overflow / large-p fallback (never for randn data): exact serial.
                float M = -3.4e38f;
                for (int i = 0; i < N; i++) M = fmaxf(M, __ldg(crow + i));
                mm = M;
                S = 0.0f;
                for (int i = 0; i < N; i++) S += __expf(__ldg(crow + i) - mm);
                invS = __frcp_rn(S);
                T = 0.0f;
                for (int i = 0; i < N; i++) {
                    float p = __expf(__ldg(crow + i) - mm) * invS;
                    T += (p > 0.0625f) ? fmaxf(log1pf(-p), LOG_CLAMP)
                                       : log1mp_series(p);
                }
            }

            float ck    = __ldg(crow + k);
            float logS  = __logf(S);
            float pk    = __expf(ck - mm) * invS;
            float logpk = fmaxf(ck - mm - logS, LOG_CLAMP);
            float tk    = (pk > 0.0625f) ? fmaxf(log1pf(-pk), LOG_CLAMP)
                                         : log1mp_series(pk);
            float ce    = -(logpk + (T - tk));

            float2 ak = ((const float2*)arow)[k];
            const float* orow = offsets + (size_t)b * (size_t)N * 2u;
            float2 ok = ((const float2*)orow)[k];
            float x0 = ok.x - (g.x - ak.x);
            float x1 = ok.y - (g.y - ak.y);
            float hu = huber1(x0) + huber1(x1);

            ce_fx += __double2ll_rn((double)ce * FXSCALE);
            hu_fx += __double2ll_rn((double)hu * FXSCALE);
        }
    }

    // One atomic pair per CTA; integer adds keep the result deterministic.
    if (t == 0) {
        atomicAdd(&g_ce_acc, (unsigned long long)ce_fx);
        atomicAdd(&g_hu_acc, (unsigned long long)hu_fx);
        __threadfence();
        unsigned int old = atomicAdd(&g_done, 1u);
        if (old == gridDim.x - 1u) {
            long long cs = (long long)atomicAdd(&g_ce_acc, 0ULL);
            long long hs = (long long)atomicAdd(&g_hu_acc, 0ULL);
            float cef = (float)((double)cs * (1.0 / FXSCALE));
            float huf = (float)((double)hs * (1.0 / FXSCALE));
            out[0] = cef + huf;
            out[1] = cef;
            out[2] = huf;
            // Reset for the next graph replay: deterministic state.
            g_ce_acc = 0ULL;
            g_hu_acc = 0ULL;
            __threadfence();
            g_done = 0u;
        }
    }
}

extern "C" void kernel_launch(void* const* d_in, const int* in_sizes, int n_in,
                              void* d_out, int out_size)
{
    const float* anchors = (const float*)d_in[0];   // (B, N, 2)
    const float* offsets = (const float*)d_in[1];   // (B, N, 2)
    const float* conf    = (const float*)d_in[2];   // (B, N)
    const float* gt      = (const float*)d_in[3];   // (B, 2)

    int B = in_sizes[3] / 2;
    int N = (B > 0) ? (in_sizes[2] / B) : 0;
    if (B <= 0 || N <= 0) return;

    int grid = (B < NCTAS) ? B : NCTAS;
    loss_kernel<<<grid, BLOCK>>>(anchors, offsets, conf, gt, N, B, (float*)d_out);
}

// round 8
// speedup vs baseline: 43.8121x; 43.8121x over previous
#include <cuda_runtime.h>

#define BLOCK 256
#define NCTAS 592               // 148 SMs * 4 resident CTAs
#define LOG_CLAMP (-100.0f)
#define HDELTA 0.04f
#define FXSCALE 16777216.0      // 2^24 fixed-point scale
#define FULL 0xffffffffu

// Deterministic cross-CTA accumulation (integer adds are associative).
__device__ unsigned long long g_ce_acc = 0ULL;
__device__ unsigned long long g_hu_acc = 0ULL;
__device__ unsigned int       g_done   = 0u;

// 4-term series for log1p(-p): -(p + p^2/2 + p^3/3 + p^4/4), |err| <= p^5/5.
__device__ __forceinline__ float log1mp4(float p) {
    return -p * (1.0f + p * (0.5f + p * (0.33333333f + p * 0.25f)));
}

__device__ __forceinline__ float huber1(float x) {
    float ax = fabsf(x);
    float quad = 0.5f * x * x;
    float lin  = HDELTA * (ax - 0.5f * HDELTA);
    return (ax <= HDELTA) ? quad : lin;
}

__global__ void __launch_bounds__(BLOCK, 4)
loss_kernel(const float* __restrict__ anchors,
            const float* __restrict__ offsets,
            const float* __restrict__ conf,
            const float* __restrict__ gt,
            int N, int B,
            float* __restrict__ out)
{
    const int t    = threadIdx.x;
    const int lane = t & 31;
    const int warp = t >> 5;

    // Double-buffered per-warp partials: warps 1..7 sail past the barrier into
    // the next row while warp 0 finishes the serial fixup of the previous one.
    __shared__ float swv[2][8];
    __shared__ int   swi[2][8];
    __shared__ float sp1[2][8], sp2[2][8], sp3[2][8], sp4[2][8], smx[2][8];

    long long ce_fx = 0, hu_fx = 0;   // thread-0 local fixed-point accumulators

    if (N == 2048) {
        int b = blockIdx.x;
        int buf = 0;
        // Prime the anchor pipeline for the first row.
        float4 pa0, pa1, pa2, pa3;
        if (b < B) {
            const float4* a4 = (const float4*)anchors + (size_t)b * 1024u;
            pa0 = a4[t]; pa1 = a4[t + 256]; pa2 = a4[t + 512]; pa3 = a4[t + 768];
        }
        while (b < B) {
            const int bn = b + gridDim.x;

            // Issue this row's conf loads now; their latency hides under argmin.
            const float4* c4 = (const float4*)conf + (size_t)b * 512u;
            float4 cv0 = c4[t];
            float4 cv1 = c4[t + 256];
            const float2 g = ((const float2*)gt)[b];

            // Consume prefetched anchors; immediately issue next row's anchors.
            float4 a0 = pa0, a1 = pa1, a2 = pa2, a3 = pa3;
            if (bn < B) {
                const float4* a4n = (const float4*)anchors + (size_t)bn * 1024u;
                pa0 = a4n[t]; pa1 = a4n[t + 256]; pa2 = a4n[t + 512]; pa3 = a4n[t + 768];
            }

            // ---- Argmin of squared distance (ascending per-thread indices:
            //      strict '<' keeps first occurrence; sqrt monotone, skipped).
            float best = 3.4e38f;
            int   bidx = 0;
            {
                float4 av[4] = {a0, a1, a2, a3};
                #pragma unroll
                for (int j = 0; j < 4; j++) {
                    int i4 = t + j * 256;
                    float dx0 = av[j].x - g.x, dy0 = av[j].y - g.y;
                    float dx1 = av[j].z - g.x, dy1 = av[j].w - g.y;
                    float d0 = fmaf(dx0, dx0, dy0 * dy0);
                    float d1 = fmaf(dx1, dx1, dy1 * dy1);
                    if (d0 < best) { best = d0; bidx = 2 * i4; }
                    if (d1 < best) { best = d1; bidx = 2 * i4 + 1; }
                }
            }

            // ---- Power sums P1..P4 of e_i = exp(c_i) (m=0) + row max.
            float p1 = 0.f, p2 = 0.f, p3 = 0.f, p4 = 0.f, lm = -3.4e38f;
            {
                float c[8];
                c[0]=cv0.x; c[1]=cv0.y; c[2]=cv0.z; c[3]=cv0.w;
                c[4]=cv1.x; c[5]=cv1.y; c[6]=cv1.z; c[7]=cv1.w;
                #pragma unroll
                for (int i = 0; i < 8; i++) {
                    lm = fmaxf(lm, c[i]);
                    float e  = __expf(c[i]);
                    float e2 = e * e;
                    p1 += e; p2 += e2; p3 += e2 * e; p4 += e2 * e2;
                }
            }

            // ---- Fused warp reduction.
            #pragma unroll
            for (int o = 16; o; o >>= 1) {
                float ov = __shfl_down_sync(FULL, best, o);
                int   oi = __shfl_down_sync(FULL, bidx, o);
                if (ov < best || (ov == best && oi < bidx)) { best = ov; bidx = oi; }
                p1 += __shfl_down_sync(FULL, p1, o);
                p2 += __shfl_down_sync(FULL, p2, o);
                p3 += __shfl_down_sync(FULL, p3, o);
                p4 += __shfl_down_sync(FULL, p4, o);
                lm  = fmaxf(lm, __shfl_down_sync(FULL, lm, o));
            }
            if (lane == 0) {
                swv[buf][warp] = best; swi[buf][warp] = bidx;
                sp1[buf][warp] = p1;   sp2[buf][warp] = p2;
                sp3[buf][warp] = p3;   sp4[buf][warp] = p4;
                smx[buf][warp] = lm;
            }
            __syncthreads();

            // ---- Thread 0: combine 8 warps, CE/Huber fixup, local accumulate.
            if (t == 0) {
                float bb = swv[buf][0]; int bi = swi[buf][0];
                float P1 = sp1[buf][0], P2 = sp2[buf][0];
                float P3 = sp3[buf][0], P4 = sp4[buf][0];
                float M  = smx[buf][0];
                #pragma unroll
                for (int w = 1; w < 8; w++) {
                    if (swv[buf][w] < bb ||
                        (swv[buf][w] == bb && swi[buf][w] < bi)) {
                        bb = swv[buf][w]; bi = swi[buf][w];
                    }
                    P1 += sp1[buf][w]; P2 += sp2[buf][w];
                    P3 += sp3[buf][w]; P4 += sp4[buf][w];
                    M = fmaxf(M, smx[buf][w]);
                }
                const int k = bi;
                const float* crow = conf + (size_t)b * 2048u;

                float S    = P1;
                float invS = __frcp_rn(S);
                float pmax = __expf(M) * invS;   // ACTUAL max p_i (tight guard)
                float T, mm = 0.0f;
                if (isfinite(S) && S > 0.0f && pmax <= 0.08f) {
                    float q2 = invS * invS;
                    T = -(1.0f
                          + 0.5f        * P2 * q2
                          + 0.33333333f * P3 * q2 * invS
                          + 0.25f       * P4 * q2 * q2);
                } else {
                    // Exact serial fallback (never for randn data).
                    float Mx = -3.4e38f;
                    for (int i = 0; i < N; i++) Mx = fmaxf(Mx, __ldg(crow + i));
                    mm = Mx;
                    S = 0.0f;
                    for (int i = 0; i < N; i++) S += __expf(__ldg(crow + i) - mm);
                    invS = __frcp_rn(S);
                    T = 0.0f;
                    for (int i = 0; i < N; i++) {
                        float p = __expf(__ldg(crow + i) - mm) * invS;
                        T += (p > 0.0625f) ? fmaxf(log1pf(-p), LOG_CLAMP)
                                           : log1mp4(p);
                    }
                }

                float ck    = __ldg(crow + k);
                float logS  = __logf(S);
                float pk    = __expf(ck - mm) * invS;
                float logpk = fmaxf(ck - mm - logS, LOG_CLAMP);
                // Same truncation as T so element k cancels exactly.
                float tk    = (pk > 0.0625f) ? fmaxf(log1pf(-pk), LOG_CLAMP)
                                             : log1mp4(pk);
                float ce    = -(logpk + (T - tk));

                float2 ak = ((const float2*)anchors)[(size_t)b * 2048u + k];
                float2 ok = ((const float2*)offsets)[(size_t)b * 2048u + k];
                float x0 = ok.x - (g.x - ak.x);
                float x1 = ok.y - (g.y - ak.y);
                float hu = huber1(x0) + huber1(x1);

                ce_fx += __double2ll_rn((double)ce * FXSCALE);
                hu_fx += __double2ll_rn((double)hu * FXSCALE);
            }
            b = bn;
            buf ^= 1;
        }
    } else {
        // Generic streaming fallback, one row per grid-stride step.
        for (int b = blockIdx.x; b < B; b += gridDim.x) {
            const float2 g = ((const float2*)gt)[b];
            const float2* a2 = (const float2*)anchors + (size_t)b * (size_t)N;
            const float*  cr = conf + (size_t)b * (size_t)N;

            float best = 3.4e38f; int bidx = 0;
            for (int i = t; i < N; i += BLOCK) {
                float2 a = a2[i];
                float dx = a.x - g.x, dy = a.y - g.y;
                float d  = fmaf(dx, dx, dy * dy);
                if (d < best || (d == best && i < bidx)) { best = d; bidx = i; }
            }
            float p1 = 0.f, p2 = 0.f, p3 = 0.f, p4 = 0.f, lm = -3.4e38f;
            for (int i = t; i < N; i += BLOCK) {
                float cc = __ldg(cr + i);
                lm = fmaxf(lm, cc);
                float e = __expf(cc), e2 = e * e;
                p1 += e; p2 += e2; p3 += e2 * e; p4 += e2 * e2;
            }
            #pragma unroll
            for (int o = 16; o; o >>= 1) {
                float ov = __shfl_down_sync(FULL, best, o);
                int   oi = __shfl_down_sync(FULL, bidx, o);
                if (ov < best || (ov == best && oi < bidx)) { best = ov; bidx = oi; }
                p1 += __shfl_down_sync(FULL, p1, o);
                p2 += __shfl_down_sync(FULL, p2, o);
                p3 += __shfl_down_sync(FULL, p3, o);
                p4 += __shfl_down_sync(FULL, p4, o);
                lm  = fmaxf(lm, __shfl_down_sync(FULL, lm, o));
            }
            if (lane == 0) {
                swv[0][warp] = best; swi[0][warp] = bidx;
                sp1[0][warp] = p1;   sp2[0][warp] = p2;
                sp3[0][warp] = p3;   sp4[0][warp] = p4;
                smx[0][warp] = lm;
            }
            __syncthreads();
            if (t == 0) {
                float bb = swv[0][0]; int bi = swi[0][0];
                float P1 = sp1[0][0], P2 = sp2[0][0], P3 = sp3[0][0], P4 = sp4[0][0];
                float M = smx[0][0];
                for (int w = 1; w < 8; w++) {
                    if (swv[0][w] < bb || (swv[0][w] == bb && swi[0][w] < bi)) {
                        bb = swv[0][w]; bi = swi[0][w];
                    }
                    P1 += sp1[0][w]; P2 += sp2[0][w]; P3 += sp3[0][w]; P4 += sp4[0][w];
                    M = fmaxf(M, smx[0][w]);
                }
                const int k = bi;
                float S = P1, invS = __frcp_rn(S);
                float pmax = __expf(M) * invS;
                float T, mm = 0.0f;
                if (isfinite(S) && S > 0.0f && pmax <= 0.08f) {
                    float q2 = invS * invS;
                    T = -(1.0f + 0.5f * P2 * q2
                          + 0.33333333f * P3 * q2 * invS
                          + 0.25f * P4 * q2 * q2);
                } else {
                    float Mx = -3.4e38f;
                    for (int i = 0; i < N; i++) Mx = fmaxf(Mx, __ldg(cr + i));
                    mm = Mx; S = 0.0f;
                    for (int i = 0; i < N; i++) S += __expf(__ldg(cr + i) - mm);
                    invS = __frcp_rn(S);
                    T = 0.0f;
                    for (int i = 0; i < N; i++) {
                        float p = __expf(__ldg(cr + i) - mm) * invS;
                        T += (p > 0.0625f) ? fmaxf(log1pf(-p), LOG_CLAMP) : log1mp4(p);
                    }
                }
                float ck    = __ldg(cr + k);
                float logS  = __logf(S);
                float pk    = __expf(ck - mm) * invS;
                float logpk = fmaxf(ck - mm - logS, LOG_CLAMP);
                float tk    = (pk > 0.0625f) ? fmaxf(log1pf(-pk), LOG_CLAMP) : log1mp4(pk);
                float ce    = -(logpk + (T - tk));
                float2 ak = ((const float2*)anchors)[(size_t)b * (size_t)N + k];
                float2 ok = ((const float2*)offsets)[(size_t)b * (size_t)N + k];
                float x0 = ok.x - (g.x - ak.x);
                float x1 = ok.y - (g.y - ak.y);
                float hu = huber1(x0) + huber1(x1);
                ce_fx += __double2ll_rn((double)ce * FXSCALE);
                hu_fx += __double2ll_rn((double)hu * FXSCALE);
            }
            __syncthreads();
        }
    }

    // One atomic pair per CTA; integer adds keep the result deterministic.
    if (t == 0) {
        atomicAdd(&g_ce_acc, (unsigned long long)ce_fx);
        atomicAdd(&g_hu_acc, (unsigned long long)hu_fx);
        __threadfence();
        unsigned int old = atomicAdd(&g_done, 1u);
        if (old == gridDim.x - 1u) {
            long long cs = (long long)atomicAdd(&g_ce_acc, 0ULL);
            long long hs = (long long)atomicAdd(&g_hu_acc, 0ULL);
            float cef = (float)((double)cs * (1.0 / FXSCALE));
            float huf = (float)((double)hs * (1.0 / FXSCALE));
            out[0] = cef + huf;
            out[1] = cef;
            out[2] = huf;
            g_ce_acc = 0ULL;
            g_hu_acc = 0ULL;
            __threadfence();
            g_done = 0u;
        }
    }
}

extern "C" void kernel_launch(void* const* d_in, const int* in_sizes, int n_in,
                              void* d_out, int out_size)
{
    const float* anchors = (const float*)d_in[0];   // (B, N, 2)
    const float* offsets = (const float*)d_in[1];   // (B, N, 2)
    const float* conf    = (const float*)d_in[2];   // (B, N)
    const float* gt      = (const float*)d_in[3];   // (B, 2)

    int B = in_sizes[3] / 2;
    int N = (B > 0) ? (in_sizes[2] / B) : 0;
    if (B <= 0 || N <= 0) return;

    int grid = (B < NCTAS) ? B : NCTAS;
    loss_kernel<<<grid, BLOCK>>>(anchors, offsets, conf, gt, N, B, (float*)d_out);
}